// round 12
// baseline (speedup 1.0000x reference)
#include <cuda_runtime.h>
#include <math.h>

#define LYRS 12
#define NH 12
#define DMODEL 768
#define DHEAD 64
#define DMLP 3072
#define NVOCAB 50257
#define NVPAD 50304
#define BATCH 2
#define SEQ 1024
#define MROWS 2048

// ---- scratch (device globals; no allocation allowed) ----
__device__ float g_resid[MROWS*DMODEL];
__device__ float g_x[MROWS*DMODEL];
__device__ float g_q[MROWS*DMODEL];
__device__ float g_k[MROWS*DMODEL];
__device__ float g_v[MROWS*DMODEL];
__device__ float g_z[MROWS*DMODEL];
__device__ float g_h[MROWS*DMLP];
// repacked K-major [N][K] tf32-rounded, k-interleaved weights
__device__ float g_bq[LYRS*DMODEL*DMODEL];
__device__ float g_bk[LYRS*DMODEL*DMODEL];
__device__ float g_bv[LYRS*DMODEL*DMODEL];
__device__ float g_bo[LYRS*DMODEL*DMODEL];
__device__ float g_bin[LYRS*DMLP*DMODEL];
__device__ float g_bout[LYRS*DMODEL*DMLP];
__device__ float g_bu[(long)NVPAD*DMODEL];

__device__ __forceinline__ float to_tf32(float x) {
    unsigned u; asm("cvt.rna.tf32.f32 %0, %1;" : "=r"(u) : "f"(x));
    return __uint_as_float(u);
}
// 16-wide k-interleave: within each 16-group, thread tig's mma operands for
// BOTH 8-k-groups are contiguous: phys = 4*t + 2*kg + hi
__device__ __forceinline__ int kperm(int c) {
    return (c & ~15) | ((c & 3) << 2) | (((c >> 3) & 1) << 1) | ((c >> 2) & 1);
}
__device__ __forceinline__ void cpa16(float* dst, const float* src) {
    unsigned d = (unsigned)__cvta_generic_to_shared(dst);
    asm volatile("cp.async.cg.shared.global [%0], [%1], 16;" :: "r"(d), "l"(src));
}

// ---- embedding ----
__global__ void embed_kernel(const int* __restrict__ tokens, const float* __restrict__ WE,
                             const float* __restrict__ Wpos, float* __restrict__ resid)
{
    int idx = blockIdx.x * blockDim.x + threadIdx.x;
    if (idx >= MROWS*DMODEL) return;
    int d = idx % DMODEL, bs = idx / DMODEL, s = bs % SEQ;
    resid[idx] = WE[(long)tokens[bs]*DMODEL + d] + Wpos[s*DMODEL + d];
}

// ---- layernorm: natural input, k-interleaved tf32 output ----
__global__ void layernorm_kernel(const float* __restrict__ in, const float* __restrict__ w,
                                 const float* __restrict__ b, float* __restrict__ out)
{
    __shared__ float sm[16];
    int row = blockIdx.x, tid = threadIdx.x;
    const float* x = in + (long)row * DMODEL;
    float s = 0.f, ss = 0.f;
    for (int i = tid; i < DMODEL; i += 256) { float v = x[i]; s += v; ss += v*v; }
    #pragma unroll
    for (int o = 16; o > 0; o >>= 1) {
        s  += __shfl_xor_sync(0xffffffffu, s,  o);
        ss += __shfl_xor_sync(0xffffffffu, ss, o);
    }
    if ((tid & 31) == 0) { sm[tid>>5] = s; sm[8 + (tid>>5)] = ss; }
    __syncthreads();
    if (tid < 8) {
        float a = sm[tid], c = sm[8+tid];
        #pragma unroll
        for (int o = 4; o > 0; o >>= 1) {
            a += __shfl_xor_sync(0xffu, a, o);
            c += __shfl_xor_sync(0xffu, c, o);
        }
        if (tid == 0) { sm[0] = a; sm[8] = c; }
    }
    __syncthreads();
    float mean = sm[0] * (1.f/DMODEL);
    float var  = sm[8] * (1.f/DMODEL) - mean*mean;
    float inv  = rsqrtf(var + 1e-5f);
    for (int i = tid; i < DMODEL; i += 256)
        out[(long)row*DMODEL + kperm(i)] = to_tf32((x[i]-mean)*inv*w[i] + b[i]);
}

// ---- weight repack: per-head [L][H][D][DH] -> [L][h*64+e][perm(D)] (tf32) ----
__global__ void trans_head(const float* __restrict__ src, float* __restrict__ dst)
{
    __shared__ float t[32][33];
    int tx = threadIdx.x, ty = threadIdx.y;
    int d0 = blockIdx.x*32, e0 = blockIdx.y*32, lh = blockIdx.z;
    int l = lh / NH, h = lh % NH;
    const float* sp = src + (long)lh*DMODEL*DHEAD;
    float* dp = dst + (long)l*DMODEL*DMODEL;
    #pragma unroll
    for (int i = 0; i < 4; i++)
        t[ty+8*i][tx] = sp[(long)(d0+ty+8*i)*DHEAD + e0+tx];
    __syncthreads();
    #pragma unroll
    for (int i = 0; i < 4; i++)
        dp[(long)(h*64 + e0+ty+8*i)*DMODEL + kperm(d0+tx)] = to_tf32(t[tx][ty+8*i]);
}

// ---- weight repack: [K,N] -> [Npad][perm(K)] transpose (tf32, zero pad) ----
__global__ void trans_kn(const float* __restrict__ src, float* __restrict__ dst,
                         int K, int N, int Npad)
{
    __shared__ float t[32][33];
    int tx = threadIdx.x, ty = threadIdx.y;
    int n0 = blockIdx.x*32, k0 = blockIdx.y*32, l = blockIdx.z;
    const float* sp = src + (long)l*K*N;
    float* dp = dst + (long)l*Npad*K;
    #pragma unroll
    for (int i = 0; i < 4; i++) {
        int n = n0+tx;
        t[ty+8*i][tx] = (n < N) ? sp[(long)(k0+ty+8*i)*N + n] : 0.f;
    }
    __syncthreads();
    #pragma unroll
    for (int i = 0; i < 4; i++)
        dp[(long)(n0+ty+8*i)*K + kperm(k0+tx)] = to_tf32(t[tx][ty+8*i]);
}

// ---- raw mma.sync tf32 GEMM: C[2048,nvalid] = A[2048,K] @ B[Npad,K]^T ----
// BK=32, XOR-swizzled smem (16B chunk g of row r at g^(r&7)), 3-stage cp.async.
// Halves barrier count vs BK=16; stage stays 32KB so 2 CTAs/SM are retained.
#define CLD 132

template<int TM, bool GELU, bool RES, bool PERMC>
__device__ __forceinline__ void gemm_core(
    const float* __restrict__ A, const float* __restrict__ B,
    const float* __restrict__ bias, const float* __restrict__ res,
    float* __restrict__ C, int K, int nvalid)
{
    extern __shared__ float smem[];
    const int STAGE = (TM + 128)*32;
    const int MF = TM/32;
    int tid = threadIdx.x, wid = tid >> 5, lane = tid & 31;
    int gid = lane >> 2, tig = lane & 3;
    int bm = blockIdx.y * TM, bn = blockIdx.x * 128;
    int wm = (wid >> 2) * (TM/2);
    int wn = (wid & 3) * 32;

    float d[TM/32][4][4];
    #pragma unroll
    for (int mi = 0; mi < MF; mi++)
        #pragma unroll
        for (int ni = 0; ni < 4; ni++)
            #pragma unroll
            for (int r = 0; r < 4; r++) d[mi][ni][r] = 0.f;

    auto loadStage = [&](int s, int it) {
        float* as = smem + s*STAGE;
        float* bs = as + TM*32;
        const float* Ag = A + (long)bm*K + it*32;
        const float* Bg = B + (long)bn*K + it*32;
        #pragma unroll
        for (int i = 0; i < TM/32; i++) {
            int idx = tid + 256*i;
            int row = idx >> 3, g = idx & 7;
            cpa16(as + row*32 + ((g ^ (row & 7)) << 2), Ag + (long)row*K + g*4);
        }
        #pragma unroll
        for (int i = 0; i < 4; i++) {
            int idx = tid + 256*i;
            int row = idx >> 3, g = idx & 7;
            cpa16(bs + row*32 + ((g ^ (row & 7)) << 2), Bg + (long)row*K + g*4);
        }
        asm volatile("cp.async.commit_group;" ::);
    };

    const int nIter = K >> 5;
    loadStage(0, 0);
    loadStage(1, 1);

    for (int it = 0; it < nIter; it++) {
        int cur = it % 3;
        if (it + 2 < nIter) asm volatile("cp.async.wait_group 1;" ::);
        else                asm volatile("cp.async.wait_group 0;" ::);
        __syncthreads();
        if (it + 2 < nIter) loadStage((it+2) % 3, it+2);

        const float* as = smem + cur*STAGE;
        const float* bs = as + TM*32;
        #pragma unroll
        for (int kp = 0; kp < 2; kp++) {
            float4 av0[TM/32], av1[TM/32], bv[4];
            #pragma unroll
            for (int mi = 0; mi < MF; mi++) {
                int r0 = wm + mi*16 + gid, r1 = r0 + 8;
                av0[mi] = *(const float4*)(as + r0*32 + (((kp*4 + tig) ^ (r0 & 7)) << 2));
                av1[mi] = *(const float4*)(as + r1*32 + (((kp*4 + tig) ^ (r1 & 7)) << 2));
            }
            #pragma unroll
            for (int ni = 0; ni < 4; ni++) {
                int rb = wn + ni*8 + gid;
                bv[ni] = *(const float4*)(bs + rb*32 + (((kp*4 + tig) ^ (rb & 7)) << 2));
            }
            #pragma unroll
            for (int mi = 0; mi < MF; mi++)
                #pragma unroll
                for (int ni = 0; ni < 4; ni++) {
                    float* dd = d[mi][ni];
                    asm volatile(
                        "mma.sync.aligned.m16n8k8.row.col.f32.tf32.tf32.f32 "
                        "{%0,%1,%2,%3}, {%4,%5,%6,%7}, {%8,%9}, {%0,%1,%2,%3};"
                        : "+f"(dd[0]), "+f"(dd[1]), "+f"(dd[2]), "+f"(dd[3])
                        : "r"(__float_as_uint(av0[mi].x)), "r"(__float_as_uint(av1[mi].x)),
                          "r"(__float_as_uint(av0[mi].y)), "r"(__float_as_uint(av1[mi].y)),
                          "r"(__float_as_uint(bv[ni].x)), "r"(__float_as_uint(bv[ni].y)));
                }
            #pragma unroll
            for (int mi = 0; mi < MF; mi++)
                #pragma unroll
                for (int ni = 0; ni < 4; ni++) {
                    float* dd = d[mi][ni];
                    asm volatile(
                        "mma.sync.aligned.m16n8k8.row.col.f32.tf32.tf32.f32 "
                        "{%0,%1,%2,%3}, {%4,%5,%6,%7}, {%8,%9}, {%0,%1,%2,%3};"
                        : "+f"(dd[0]), "+f"(dd[1]), "+f"(dd[2]), "+f"(dd[3])
                        : "r"(__float_as_uint(av0[mi].z)), "r"(__float_as_uint(av1[mi].z)),
                          "r"(__float_as_uint(av0[mi].w)), "r"(__float_as_uint(av1[mi].w)),
                          "r"(__float_as_uint(bv[ni].z)), "r"(__float_as_uint(bv[ni].w)));
                }
        }
        __syncthreads();
    }

    // epilogue: stage through smem (alias stages), then guarded fused store
    float* Cs = smem;
    #pragma unroll
    for (int mi = 0; mi < MF; mi++)
        #pragma unroll
        for (int ni = 0; ni < 4; ni++) {
            float* dd = d[mi][ni];
            int col = wn + ni*8 + 2*tig;
            float* p0 = Cs + (wm + mi*16 + gid)*CLD + col;
            float* p1 = Cs + (wm + mi*16 + gid + 8)*CLD + col;
            p0[0] = dd[0]; p0[1] = dd[1];
            p1[0] = dd[2]; p1[1] = dd[3];
        }
    __syncthreads();

    for (int idx = tid; idx < TM*128; idx += 256) {
        int r = idx >> 7, c = idx & 127;
        int n = bn + c;
        if (n < nvalid) {
            float v = Cs[r*CLD + c] + bias[n];
            long gr = bm + r;
            if (RES) v += res[gr*nvalid + n];
            if (GELU) {
                float t3 = v*v*v;
                v = 0.5f*v*(1.f + tanhf(0.7978845608028654f*(v + 0.044715f*t3)));
                v = to_tf32(v);
            }
            C[gr*nvalid + (PERMC ? kperm(n) : n)] = v;
        }
    }
}

template<int TM, bool GELU, bool RES, bool PERMC>
__global__ void __launch_bounds__(256, 2) gemm_w(
    const float* __restrict__ A, const float* __restrict__ B,
    const float* __restrict__ bias, const float* __restrict__ res,
    float* __restrict__ C, int K, int nvalid)
{
    gemm_core<TM,GELU,RES,PERMC>(A, B, bias, res, C, K, nvalid);
}

__global__ void __launch_bounds__(256, 2) qkv_w(
    const float* __restrict__ A,
    const float* __restrict__ Bq, const float* __restrict__ Bk, const float* __restrict__ Bv,
    const float* __restrict__ bq, const float* __restrict__ bk, const float* __restrict__ bv,
    float* __restrict__ q, float* __restrict__ k, float* __restrict__ v)
{
    const float* B; const float* bias; float* C;
    int z = blockIdx.z;
    if (z == 0)      { B = Bq; bias = bq; C = q; }
    else if (z == 1) { B = Bk; bias = bk; C = k; }
    else             { B = Bv; bias = bv; C = v; }
    gemm_core<128,false,false,false>(A, B, bias, nullptr, C, DMODEL, DMODEL);
}

// ---- flash attention: block per (64 q-rows, h, b); 64 threads, 1 row/thread ----
__global__ void __launch_bounds__(64) flash_kernel(
    const float* __restrict__ q, const float* __restrict__ k,
    const float* __restrict__ v, float* __restrict__ z)
{
    __shared__ float Qs[64][68];
    __shared__ float Ks[32][68];
    __shared__ float Vs[32][68];
    __shared__ float Ss[64][33];
    int tid = threadIdx.x;
    int qt = blockIdx.x, h = blockIdx.y, b = blockIdx.z;
    int qi = qt*64 + tid;
    long qrow = (long)(b*SEQ + qi)*DMODEL + h*DHEAD;

    for (int r = 0; r < 64; r++)
        Qs[r][tid] = q[(long)(b*SEQ + qt*64 + r)*DMODEL + h*DHEAD + tid];

    float o[64];
    #pragma unroll
    for (int e = 0; e < 64; e++) o[e] = 0.f;
    float m = -1e30f, l = 0.f;

    int ntiles = qt*2 + 2;
    for (int kt = 0; kt < ntiles; kt++) {
        __syncthreads();
        long kb = (long)(b*SEQ + kt*32)*DMODEL + h*DHEAD;
        for (int r = 0; r < 32; r++) {
            Ks[r][tid] = k[kb + (long)r*DMODEL + tid];
            Vs[r][tid] = v[kb + (long)r*DMODEL + tid];
        }
        __syncthreads();
        for (int jg = 0; jg < 4; jg++) {
            float sa[8];
            #pragma unroll
            for (int i = 0; i < 8; i++) sa[i] = 0.f;
            for (int e4 = 0; e4 < 16; e4++) {
                float4 qv = *(const float4*)&Qs[tid][e4*4];
                #pragma unroll
                for (int i = 0; i < 8; i++) {
                    float4 kk = *(const float4*)&Ks[jg*8 + i][e4*4];
                    sa[i] += qv.x*kk.x + qv.y*kk.y + qv.z*kk.z + qv.w*kk.w;
                }
            }
            #pragma unroll
            for (int i = 0; i < 8; i++) Ss[tid][jg*8 + i] = sa[i];
        }
        float tmax = -1e30f;
        for (int j = 0; j < 32; j++) {
            int kj = kt*32 + j;
            float sv = (kj <= qi) ? Ss[tid][j]*0.125f : -1e30f;
            Ss[tid][j] = sv;
            tmax = fmaxf(tmax, sv);
        }
        float mn = fmaxf(m, tmax);
        float sc = __expf(m - mn);
        float ts = 0.f;
        for (int j = 0; j < 32; j++) {
            float p = __expf(Ss[tid][j] - mn);
            Ss[tid][j] = p;
            ts += p;
        }
        l = l*sc + ts;
        m = mn;
        #pragma unroll
        for (int e = 0; e < 64; e++) o[e] *= sc;
        for (int j = 0; j < 32; j++) {
            float p = Ss[tid][j];
            #pragma unroll
            for (int e4 = 0; e4 < 16; e4++) {
                float4 vv = *(const float4*)&Vs[j][e4*4];
                o[e4*4+0] += p*vv.x; o[e4*4+1] += p*vv.y;
                o[e4*4+2] += p*vv.z; o[e4*4+3] += p*vv.w;
            }
        }
    }
    float inv = 1.f / l;
    #pragma unroll
    for (int e = 0; e < 64; e++) z[qrow + kperm(e)] = to_tf32(o[e]*inv);
}

// smem bytes: max(3 stages, epilogue restage)
#define SMB128 (3*(128+128)*32*4 > 128*CLD*4 ? 3*(128+128)*32*4 : 128*CLD*4)  // 98304
#define SMB64  (3*(64+128)*32*4 > 64*CLD*4 ? 3*(64+128)*32*4 : 64*CLD*4)      // 73728

extern "C" void kernel_launch(void* const* d_in, const int* in_sizes, int n_in,
                              void* d_out, int out_size)
{
    const int*   tokens = (const int*)  d_in[0];
    const float* W_E    = (const float*)d_in[1];
    const float* W_pos  = (const float*)d_in[2];
    const float* ln1_w  = (const float*)d_in[3];
    const float* ln1_b  = (const float*)d_in[4];
    const float* W_Q    = (const float*)d_in[5];
    const float* b_Q    = (const float*)d_in[6];
    const float* W_K    = (const float*)d_in[7];
    const float* b_K    = (const float*)d_in[8];
    const float* W_V    = (const float*)d_in[9];
    const float* b_V    = (const float*)d_in[10];
    const float* W_O    = (const float*)d_in[11];
    const float* b_O    = (const float*)d_in[12];
    const float* ln2_w  = (const float*)d_in[13];
    const float* ln2_b  = (const float*)d_in[14];
    const float* W_in   = (const float*)d_in[15];
    const float* b_in   = (const float*)d_in[16];
    const float* W_out  = (const float*)d_in[17];
    const float* b_out  = (const float*)d_in[18];
    const float* lnf_w  = (const float*)d_in[19];
    const float* lnf_b  = (const float*)d_in[20];
    const float* W_U    = (const float*)d_in[21];
    const float* b_U    = (const float*)d_in[22];
    float* out = (float*)d_out;

    float *p_resid, *p_x, *p_q, *p_k, *p_v, *p_z, *p_h;
    float *p_bq, *p_bk, *p_bv, *p_bo, *p_bin, *p_bout, *p_bu;
    cudaGetSymbolAddress((void**)&p_resid, g_resid);
    cudaGetSymbolAddress((void**)&p_x, g_x);
    cudaGetSymbolAddress((void**)&p_q, g_q);
    cudaGetSymbolAddress((void**)&p_k, g_k);
    cudaGetSymbolAddress((void**)&p_v, g_v);
    cudaGetSymbolAddress((void**)&p_z, g_z);
    cudaGetSymbolAddress((void**)&p_h, g_h);
    cudaGetSymbolAddress((void**)&p_bq, g_bq);
    cudaGetSymbolAddress((void**)&p_bk, g_bk);
    cudaGetSymbolAddress((void**)&p_bv, g_bv);
    cudaGetSymbolAddress((void**)&p_bo, g_bo);
    cudaGetSymbolAddress((void**)&p_bin, g_bin);
    cudaGetSymbolAddress((void**)&p_bout, g_bout);
    cudaGetSymbolAddress((void**)&p_bu, g_bu);

    cudaFuncSetAttribute((const void*)gemm_w<128,false,false,false>, cudaFuncAttributeMaxDynamicSharedMemorySize, SMB128);
    cudaFuncSetAttribute((const void*)gemm_w<128,true,false,true>,   cudaFuncAttributeMaxDynamicSharedMemorySize, SMB128);
    cudaFuncSetAttribute((const void*)gemm_w<64,false,true,false>,   cudaFuncAttributeMaxDynamicSharedMemorySize, SMB64);
    cudaFuncSetAttribute((const void*)qkv_w,                         cudaFuncAttributeMaxDynamicSharedMemorySize, SMB128);

    dim3 tb(32, 8);
    trans_head<<<dim3(24, 2, LYRS*NH), tb>>>(W_Q, p_bq);
    trans_head<<<dim3(24, 2, LYRS*NH), tb>>>(W_K, p_bk);
    trans_head<<<dim3(24, 2, LYRS*NH), tb>>>(W_V, p_bv);
    trans_kn<<<dim3(24, 24, LYRS), tb>>>(W_O, p_bo, DMODEL, DMODEL, DMODEL);
    trans_kn<<<dim3(96, 24, LYRS), tb>>>(W_in, p_bin, DMODEL, DMLP, DMLP);
    trans_kn<<<dim3(24, 96, LYRS), tb>>>(W_out, p_bout, DMLP, DMODEL, DMODEL);
    trans_kn<<<dim3(NVPAD/32, 24, 1), tb>>>(W_U, p_bu, DMODEL, NVOCAB, NVPAD);

    embed_kernel<<<(MROWS*DMODEL + 255)/256, 256>>>(tokens, W_E, W_pos, p_resid);

    for (int l = 0; l < LYRS; l++) {
        layernorm_kernel<<<MROWS, 256>>>(p_resid, ln1_w + l*DMODEL, ln1_b + l*DMODEL, p_x);

        qkv_w<<<dim3(6, 16, 3), 256, SMB128>>>(
            p_x,
            p_bq + (long)l*DMODEL*DMODEL, p_bk + (long)l*DMODEL*DMODEL, p_bv + (long)l*DMODEL*DMODEL,
            b_Q + l*DMODEL, b_K + l*DMODEL, b_V + l*DMODEL,
            p_q, p_k, p_v);

        flash_kernel<<<dim3(SEQ/64, NH, BATCH), 64>>>(p_q, p_k, p_v, p_z);

        gemm_w<64,false,true,false><<<dim3(6, 32), 256, SMB64>>>(
            p_z, p_bo + (long)l*DMODEL*DMODEL, b_O + l*DMODEL, p_resid, p_resid,
            DMODEL, DMODEL);

        layernorm_kernel<<<MROWS, 256>>>(p_resid, ln2_w + l*DMODEL, ln2_b + l*DMODEL, p_x);

        gemm_w<128,true,false,true><<<dim3(24, 16), 256, SMB128>>>(
            p_x, p_bin + (long)l*DMLP*DMODEL, b_in + l*DMLP, nullptr, p_h,
            DMODEL, DMLP);

        gemm_w<64,false,true,false><<<dim3(6, 32), 256, SMB64>>>(
            p_h, p_bout + (long)l*DMODEL*DMLP, b_out + l*DMODEL, p_resid, p_resid,
            DMLP, DMODEL);
    }

    layernorm_kernel<<<MROWS, 256>>>(p_resid, lnf_w, lnf_b, p_x);

    gemm_w<128,false,false,false><<<dim3(NVPAD/128, 16), 256, SMB128>>>(
        p_x, p_bu, b_U, nullptr, out, DMODEL, NVOCAB);
}

// round 13
// speedup vs baseline: 1.2452x; 1.2452x over previous
#include <cuda_runtime.h>
#include <cuda_fp16.h>
#include <math.h>

#define LYRS 12
#define NH 12
#define DMODEL 768
#define DHEAD 64
#define DMLP 3072
#define NVOCAB 50257
#define NVPAD 50304
#define BATCH 2
#define SEQ 1024
#define MROWS 2048

// ---- scratch (device globals; no allocation allowed) ----
__device__ float  g_resid[MROWS*DMODEL];
__device__ __half g_x[MROWS*DMODEL];
__device__ float  g_q[MROWS*DMODEL];
__device__ float  g_k[MROWS*DMODEL];
__device__ float  g_v[MROWS*DMODEL];
__device__ __half g_z[MROWS*DMODEL];
__device__ __half g_h[MROWS*DMLP];
// repacked K-major [N][K] fp16, 32-wide k-interleaved weights
__device__ __half g_bq[LYRS*DMODEL*DMODEL];
__device__ __half g_bk[LYRS*DMODEL*DMODEL];
__device__ __half g_bv[LYRS*DMODEL*DMODEL];
__device__ __half g_bo[LYRS*DMODEL*DMODEL];
__device__ __half g_bin[LYRS*DMLP*DMODEL];
__device__ __half g_bout[LYRS*DMODEL*DMLP];
__device__ __half g_bu[(long)NVPAD*DMODEL];

// 32-wide k-interleave for fp16 m16n8k16 fragments:
// thread tig's halves for both k16-steps are contiguous (one LDS.128).
// phys = t<<3 | kg<<2 | hi<<1 | lo  (t=bits1-2, hi=bit3, kg=bit4, lo=bit0)
__device__ __forceinline__ int kperm(int c) {
    return (c & ~31) | (((c >> 1) & 3) << 3) | (((c >> 4) & 1) << 2)
         | (((c >> 3) & 1) << 1) | (c & 1);
}
__device__ __forceinline__ void cpa16(__half* dst, const __half* src) {
    unsigned d = (unsigned)__cvta_generic_to_shared(dst);
    asm volatile("cp.async.cg.shared.global [%0], [%1], 16;" :: "r"(d), "l"(src));
}

// ---- embedding ----
__global__ void embed_kernel(const int* __restrict__ tokens, const float* __restrict__ WE,
                             const float* __restrict__ Wpos, float* __restrict__ resid)
{
    int idx = blockIdx.x * blockDim.x + threadIdx.x;
    if (idx >= MROWS*DMODEL) return;
    int d = idx % DMODEL, bs = idx / DMODEL, s = bs % SEQ;
    resid[idx] = WE[(long)tokens[bs]*DMODEL + d] + Wpos[s*DMODEL + d];
}

// ---- layernorm: fp32 input, fp16 k-interleaved output ----
__global__ void layernorm_kernel(const float* __restrict__ in, const float* __restrict__ w,
                                 const float* __restrict__ b, __half* __restrict__ out)
{
    __shared__ float sm[16];
    int row = blockIdx.x, tid = threadIdx.x;
    const float* x = in + (long)row * DMODEL;
    float s = 0.f, ss = 0.f;
    for (int i = tid; i < DMODEL; i += 256) { float v = x[i]; s += v; ss += v*v; }
    #pragma unroll
    for (int o = 16; o > 0; o >>= 1) {
        s  += __shfl_xor_sync(0xffffffffu, s,  o);
        ss += __shfl_xor_sync(0xffffffffu, ss, o);
    }
    if ((tid & 31) == 0) { sm[tid>>5] = s; sm[8 + (tid>>5)] = ss; }
    __syncthreads();
    if (tid < 8) {
        float a = sm[tid], c = sm[8+tid];
        #pragma unroll
        for (int o = 4; o > 0; o >>= 1) {
            a += __shfl_xor_sync(0xffu, a, o);
            c += __shfl_xor_sync(0xffu, c, o);
        }
        if (tid == 0) { sm[0] = a; sm[8] = c; }
    }
    __syncthreads();
    float mean = sm[0] * (1.f/DMODEL);
    float var  = sm[8] * (1.f/DMODEL) - mean*mean;
    float inv  = rsqrtf(var + 1e-5f);
    for (int i = tid; i < DMODEL; i += 256)
        out[(long)row*DMODEL + kperm(i)] = __float2half((x[i]-mean)*inv*w[i] + b[i]);
}

// ---- weight repack: per-head [L][H][D][DH] -> [L][h*64+e][perm(D)] (fp16) ----
__global__ void trans_head(const float* __restrict__ src, __half* __restrict__ dst)
{
    __shared__ float t[32][33];
    int tx = threadIdx.x, ty = threadIdx.y;
    int d0 = blockIdx.x*32, e0 = blockIdx.y*32, lh = blockIdx.z;
    int l = lh / NH, h = lh % NH;
    const float* sp = src + (long)lh*DMODEL*DHEAD;
    __half* dp = dst + (long)l*DMODEL*DMODEL;
    #pragma unroll
    for (int i = 0; i < 4; i++)
        t[ty+8*i][tx] = sp[(long)(d0+ty+8*i)*DHEAD + e0+tx];
    __syncthreads();
    #pragma unroll
    for (int i = 0; i < 4; i++)
        dp[(long)(h*64 + e0+ty+8*i)*DMODEL + kperm(d0+tx)] = __float2half(t[tx][ty+8*i]);
}

// ---- weight repack: [K,N] -> [Npad][perm(K)] transpose (fp16, zero pad) ----
__global__ void trans_kn(const float* __restrict__ src, __half* __restrict__ dst,
                         int K, int N, int Npad)
{
    __shared__ float t[32][33];
    int tx = threadIdx.x, ty = threadIdx.y;
    int n0 = blockIdx.x*32, k0 = blockIdx.y*32, l = blockIdx.z;
    const float* sp = src + (long)l*K*N;
    __half* dp = dst + (long)l*Npad*K;
    #pragma unroll
    for (int i = 0; i < 4; i++) {
        int n = n0+tx;
        t[ty+8*i][tx] = (n < N) ? sp[(long)(k0+ty+8*i)*N + n] : 0.f;
    }
    __syncthreads();
    #pragma unroll
    for (int i = 0; i < 4; i++)
        dp[(long)(n0+ty+8*i)*K + kperm(k0+tx)] = __float2half(t[tx][ty+8*i]);
}

// ---- fp16 mma.sync GEMM: C[2048,nvalid] = A[2048,K] @ B[Npad,K]^T ----
// A/B fp16, 32-wide k-interleaved. BK=32 halves (2 x k16 steps), rows padded
// 64B->80B (bank-conflict-free LDS.128). 3-stage cp.async, 8 warps.
#define KLDH 40
#define CLD 132

template<int TM, bool GELU, bool RES, bool OUTH>
__device__ __forceinline__ void gemm_core(
    const __half* __restrict__ A, const __half* __restrict__ B,
    const float* __restrict__ bias, const float* __restrict__ res,
    void* __restrict__ Cv, int K, int nvalid)
{
    extern __shared__ char smraw[];
    __half* smh = (__half*)smraw;
    const int STAGEH = (TM + 128)*KLDH;
    const int MF = TM/32;
    int tid = threadIdx.x, wid = tid >> 5, lane = tid & 31;
    int gid = lane >> 2, tig = lane & 3;
    int bm = blockIdx.y * TM, bn = blockIdx.x * 128;
    int wm = (wid >> 2) * (TM/2);
    int wn = (wid & 3) * 32;

    float d[TM/32][4][4];
    #pragma unroll
    for (int mi = 0; mi < MF; mi++)
        #pragma unroll
        for (int ni = 0; ni < 4; ni++)
            #pragma unroll
            for (int r = 0; r < 4; r++) d[mi][ni][r] = 0.f;

    auto loadStage = [&](int s, int it) {
        __half* as = smh + s*STAGEH;
        __half* bs = as + TM*KLDH;
        const __half* Ag = A + (long)bm*K + it*32;
        const __half* Bg = B + (long)bn*K + it*32;
        #pragma unroll
        for (int i = 0; i < TM/64; i++) {
            int idx = tid + 256*i;
            int row = idx >> 2, c = idx & 3;           // 16B chunk = 8 halves
            cpa16(as + row*KLDH + c*8, Ag + (long)row*K + c*8);
        }
        #pragma unroll
        for (int i = 0; i < 2; i++) {
            int idx = tid + 256*i;
            int row = idx >> 2, c = idx & 3;
            cpa16(bs + row*KLDH + c*8, Bg + (long)row*K + c*8);
        }
        asm volatile("cp.async.commit_group;" ::);
    };

    const int nIter = K >> 5;
    loadStage(0, 0);
    loadStage(1, 1);

    for (int it = 0; it < nIter; it++) {
        int cur = it % 3;
        if (it + 2 < nIter) asm volatile("cp.async.wait_group 1;" ::);
        else                asm volatile("cp.async.wait_group 0;" ::);
        __syncthreads();
        if (it + 2 < nIter) loadStage((it+2) % 3, it+2);

        const __half* as = smh + cur*STAGEH;
        const __half* bs = as + TM*KLDH;
        // one LDS.128 per row covers both k16 steps
        uint4 av0[TM/32], av1[TM/32], bv[4];
        #pragma unroll
        for (int mi = 0; mi < MF; mi++) {
            av0[mi] = ((const uint4*)(as + (wm + mi*16 + gid)*KLDH))[tig];
            av1[mi] = ((const uint4*)(as + (wm + mi*16 + gid + 8)*KLDH))[tig];
        }
        #pragma unroll
        for (int ni = 0; ni < 4; ni++)
            bv[ni] = ((const uint4*)(bs + (wn + ni*8 + gid)*KLDH))[tig];

        #pragma unroll
        for (int mi = 0; mi < MF; mi++)
            #pragma unroll
            for (int ni = 0; ni < 4; ni++) {
                float* dd = d[mi][ni];
                asm volatile(
                    "mma.sync.aligned.m16n8k16.row.col.f32.f16.f16.f32 "
                    "{%0,%1,%2,%3}, {%4,%5,%6,%7}, {%8,%9}, {%0,%1,%2,%3};"
                    : "+f"(dd[0]), "+f"(dd[1]), "+f"(dd[2]), "+f"(dd[3])
                    : "r"(av0[mi].x), "r"(av1[mi].x), "r"(av0[mi].y), "r"(av1[mi].y),
                      "r"(bv[ni].x), "r"(bv[ni].y));
            }
        #pragma unroll
        for (int mi = 0; mi < MF; mi++)
            #pragma unroll
            for (int ni = 0; ni < 4; ni++) {
                float* dd = d[mi][ni];
                asm volatile(
                    "mma.sync.aligned.m16n8k16.row.col.f32.f16.f16.f32 "
                    "{%0,%1,%2,%3}, {%4,%5,%6,%7}, {%8,%9}, {%0,%1,%2,%3};"
                    : "+f"(dd[0]), "+f"(dd[1]), "+f"(dd[2]), "+f"(dd[3])
                    : "r"(av0[mi].z), "r"(av1[mi].z), "r"(av0[mi].w), "r"(av1[mi].w),
                      "r"(bv[ni].z), "r"(bv[ni].w));
            }
        __syncthreads();
    }

    // epilogue: stage through smem (alias stages), then guarded fused store
    float* Cs = (float*)smraw;
    #pragma unroll
    for (int mi = 0; mi < MF; mi++)
        #pragma unroll
        for (int ni = 0; ni < 4; ni++) {
            float* dd = d[mi][ni];
            int col = wn + ni*8 + 2*tig;
            float* p0 = Cs + (wm + mi*16 + gid)*CLD + col;
            float* p1 = Cs + (wm + mi*16 + gid + 8)*CLD + col;
            p0[0] = dd[0]; p0[1] = dd[1];
            p1[0] = dd[2]; p1[1] = dd[3];
        }
    __syncthreads();

    for (int idx = tid; idx < TM*128; idx += 256) {
        int r = idx >> 7, c = idx & 127;
        int n = bn + c;
        if (n < nvalid) {
            float v = Cs[r*CLD + c] + bias[n];
            long gr = bm + r;
            if (RES) v += res[gr*nvalid + n];
            if (GELU) {
                float t3 = v*v*v;
                v = 0.5f*v*(1.f + tanhf(0.7978845608028654f*(v + 0.044715f*t3)));
            }
            if (OUTH) ((__half*)Cv)[gr*nvalid + kperm(n)] = __float2half(v);
            else      ((float*)Cv)[gr*nvalid + n] = v;
        }
    }
}

template<int TM, bool GELU, bool RES, bool OUTH>
__global__ void __launch_bounds__(256, 2) gemm_w(
    const __half* __restrict__ A, const __half* __restrict__ B,
    const float* __restrict__ bias, const float* __restrict__ res,
    void* __restrict__ C, int K, int nvalid)
{
    gemm_core<TM,GELU,RES,OUTH>(A, B, bias, res, C, K, nvalid);
}

__global__ void __launch_bounds__(256, 2) qkv_w(
    const __half* __restrict__ A,
    const __half* __restrict__ Bq, const __half* __restrict__ Bk, const __half* __restrict__ Bv,
    const float* __restrict__ bq, const float* __restrict__ bk, const float* __restrict__ bv,
    float* __restrict__ q, float* __restrict__ k, float* __restrict__ v)
{
    const __half* B; const float* bias; float* C;
    int z = blockIdx.z;
    if (z == 0)      { B = Bq; bias = bq; C = q; }
    else if (z == 1) { B = Bk; bias = bk; C = k; }
    else             { B = Bv; bias = bv; C = v; }
    gemm_core<128,false,false,false>(A, B, bias, nullptr, C, DMODEL, DMODEL);
}

// ---- flash attention: block per (64 q-rows, h, b); 64 threads, 1 row/thread ----
// q/k/v fp32 natural; z written fp16 k-interleaved (A of out-proj).
__global__ void __launch_bounds__(64) flash_kernel(
    const float* __restrict__ q, const float* __restrict__ k,
    const float* __restrict__ v, __half* __restrict__ z)
{
    __shared__ float Qs[64][68];
    __shared__ float Ks[32][68];
    __shared__ float Vs[32][68];
    __shared__ float Ss[64][33];
    int tid = threadIdx.x;
    int qt = blockIdx.x, h = blockIdx.y, b = blockIdx.z;
    int qi = qt*64 + tid;
    long qrow = (long)(b*SEQ + qi)*DMODEL + h*DHEAD;

    for (int r = 0; r < 64; r++)
        Qs[r][tid] = q[(long)(b*SEQ + qt*64 + r)*DMODEL + h*DHEAD + tid];

    float o[64];
    #pragma unroll
    for (int e = 0; e < 64; e++) o[e] = 0.f;
    float m = -1e30f, l = 0.f;

    int ntiles = qt*2 + 2;
    for (int kt = 0; kt < ntiles; kt++) {
        __syncthreads();
        long kb = (long)(b*SEQ + kt*32)*DMODEL + h*DHEAD;
        for (int r = 0; r < 32; r++) {
            Ks[r][tid] = k[kb + (long)r*DMODEL + tid];
            Vs[r][tid] = v[kb + (long)r*DMODEL + tid];
        }
        __syncthreads();
        for (int jg = 0; jg < 4; jg++) {
            float sa[8];
            #pragma unroll
            for (int i = 0; i < 8; i++) sa[i] = 0.f;
            for (int e4 = 0; e4 < 16; e4++) {
                float4 qv = *(const float4*)&Qs[tid][e4*4];
                #pragma unroll
                for (int i = 0; i < 8; i++) {
                    float4 kk = *(const float4*)&Ks[jg*8 + i][e4*4];
                    sa[i] += qv.x*kk.x + qv.y*kk.y + qv.z*kk.z + qv.w*kk.w;
                }
            }
            #pragma unroll
            for (int i = 0; i < 8; i++) Ss[tid][jg*8 + i] = sa[i];
        }
        float tmax = -1e30f;
        for (int j = 0; j < 32; j++) {
            int kj = kt*32 + j;
            float sv = (kj <= qi) ? Ss[tid][j]*0.125f : -1e30f;
            Ss[tid][j] = sv;
            tmax = fmaxf(tmax, sv);
        }
        float mn = fmaxf(m, tmax);
        float sc = __expf(m - mn);
        float ts = 0.f;
        for (int j = 0; j < 32; j++) {
            float p = __expf(Ss[tid][j] - mn);
            Ss[tid][j] = p;
            ts += p;
        }
        l = l*sc + ts;
        m = mn;
        #pragma unroll
        for (int e = 0; e < 64; e++) o[e] *= sc;
        for (int j = 0; j < 32; j++) {
            float p = Ss[tid][j];
            #pragma unroll
            for (int e4 = 0; e4 < 16; e4++) {
                float4 vv = *(const float4*)&Vs[j][e4*4];
                o[e4*4+0] += p*vv.x; o[e4*4+1] += p*vv.y;
                o[e4*4+2] += p*vv.z; o[e4*4+3] += p*vv.w;
            }
        }
    }
    float inv = 1.f / l;
    #pragma unroll
    for (int e = 0; e < 64; e++) z[qrow + kperm(e)] = __float2half(o[e]*inv);
}

// smem bytes: max(3 fp16 stages, fp32 epilogue restage)
#define SMB128 (128*CLD*4)                                  // 67584 (stages: 61440)
#define SMB64  (3*(64+128)*KLDH*2 > 64*CLD*4 ? 3*(64+128)*KLDH*2 : 64*CLD*4)  // 46080

extern "C" void kernel_launch(void* const* d_in, const int* in_sizes, int n_in,
                              void* d_out, int out_size)
{
    const int*   tokens = (const int*)  d_in[0];
    const float* W_E    = (const float*)d_in[1];
    const float* W_pos  = (const float*)d_in[2];
    const float* ln1_w  = (const float*)d_in[3];
    const float* ln1_b  = (const float*)d_in[4];
    const float* W_Q    = (const float*)d_in[5];
    const float* b_Q    = (const float*)d_in[6];
    const float* W_K    = (const float*)d_in[7];
    const float* b_K    = (const float*)d_in[8];
    const float* W_V    = (const float*)d_in[9];
    const float* b_V    = (const float*)d_in[10];
    const float* W_O    = (const float*)d_in[11];
    const float* b_O    = (const float*)d_in[12];
    const float* ln2_w  = (const float*)d_in[13];
    const float* ln2_b  = (const float*)d_in[14];
    const float* W_in   = (const float*)d_in[15];
    const float* b_in   = (const float*)d_in[16];
    const float* W_out  = (const float*)d_in[17];
    const float* b_out  = (const float*)d_in[18];
    const float* lnf_w  = (const float*)d_in[19];
    const float* lnf_b  = (const float*)d_in[20];
    const float* W_U    = (const float*)d_in[21];
    const float* b_U    = (const float*)d_in[22];
    float* out = (float*)d_out;

    float *p_resid, *p_q, *p_k, *p_v;
    __half *p_x, *p_z, *p_h;
    __half *p_bq, *p_bk, *p_bv, *p_bo, *p_bin, *p_bout, *p_bu;
    cudaGetSymbolAddress((void**)&p_resid, g_resid);
    cudaGetSymbolAddress((void**)&p_x, g_x);
    cudaGetSymbolAddress((void**)&p_q, g_q);
    cudaGetSymbolAddress((void**)&p_k, g_k);
    cudaGetSymbolAddress((void**)&p_v, g_v);
    cudaGetSymbolAddress((void**)&p_z, g_z);
    cudaGetSymbolAddress((void**)&p_h, g_h);
    cudaGetSymbolAddress((void**)&p_bq, g_bq);
    cudaGetSymbolAddress((void**)&p_bk, g_bk);
    cudaGetSymbolAddress((void**)&p_bv, g_bv);
    cudaGetSymbolAddress((void**)&p_bo, g_bo);
    cudaGetSymbolAddress((void**)&p_bin, g_bin);
    cudaGetSymbolAddress((void**)&p_bout, g_bout);
    cudaGetSymbolAddress((void**)&p_bu, g_bu);

    cudaFuncSetAttribute((const void*)gemm_w<128,false,false,false>, cudaFuncAttributeMaxDynamicSharedMemorySize, SMB128);
    cudaFuncSetAttribute((const void*)gemm_w<128,true,false,true>,   cudaFuncAttributeMaxDynamicSharedMemorySize, SMB128);
    cudaFuncSetAttribute((const void*)gemm_w<64,false,true,false>,   cudaFuncAttributeMaxDynamicSharedMemorySize, SMB64);
    cudaFuncSetAttribute((const void*)qkv_w,                         cudaFuncAttributeMaxDynamicSharedMemorySize, SMB128);

    dim3 tb(32, 8);
    trans_head<<<dim3(24, 2, LYRS*NH), tb>>>(W_Q, p_bq);
    trans_head<<<dim3(24, 2, LYRS*NH), tb>>>(W_K, p_bk);
    trans_head<<<dim3(24, 2, LYRS*NH), tb>>>(W_V, p_bv);
    trans_kn<<<dim3(24, 24, LYRS), tb>>>(W_O, p_bo, DMODEL, DMODEL, DMODEL);
    trans_kn<<<dim3(96, 24, LYRS), tb>>>(W_in, p_bin, DMODEL, DMLP, DMLP);
    trans_kn<<<dim3(24, 96, LYRS), tb>>>(W_out, p_bout, DMLP, DMODEL, DMODEL);
    trans_kn<<<dim3(NVPAD/32, 24, 1), tb>>>(W_U, p_bu, DMODEL, NVOCAB, NVPAD);

    embed_kernel<<<(MROWS*DMODEL + 255)/256, 256>>>(tokens, W_E, W_pos, p_resid);

    for (int l = 0; l < LYRS; l++) {
        layernorm_kernel<<<MROWS, 256>>>(p_resid, ln1_w + l*DMODEL, ln1_b + l*DMODEL, p_x);

        qkv_w<<<dim3(6, 16, 3), 256, SMB128>>>(
            p_x,
            p_bq + (long)l*DMODEL*DMODEL, p_bk + (long)l*DMODEL*DMODEL, p_bv + (long)l*DMODEL*DMODEL,
            b_Q + l*DMODEL, b_K + l*DMODEL, b_V + l*DMODEL,
            p_q, p_k, p_v);

        flash_kernel<<<dim3(SEQ/64, NH, BATCH), 64>>>(p_q, p_k, p_v, p_z);

        gemm_w<64,false,true,false><<<dim3(6, 32), 256, SMB64>>>(
            p_z, p_bo + (long)l*DMODEL*DMODEL, b_O + l*DMODEL, p_resid, p_resid,
            DMODEL, DMODEL);

        layernorm_kernel<<<MROWS, 256>>>(p_resid, ln2_w + l*DMODEL, ln2_b + l*DMODEL, p_x);

        gemm_w<128,true,false,true><<<dim3(24, 16), 256, SMB128>>>(
            p_x, p_bin + (long)l*DMLP*DMODEL, b_in + l*DMLP, nullptr, p_h,
            DMODEL, DMLP);

        gemm_w<64,false,true,false><<<dim3(6, 32), 256, SMB64>>>(
            p_h, p_bout + (long)l*DMODEL*DMLP, b_out + l*DMODEL, p_resid, p_resid,
            DMLP, DMODEL);
    }

    layernorm_kernel<<<MROWS, 256>>>(p_resid, lnf_w, lnf_b, p_x);

    gemm_w<128,false,false,false><<<dim3(NVPAD/128, 16), 256, SMB128>>>(
        p_x, p_bu, b_U, nullptr, out, DMODEL, NVOCAB);
}

// round 16
// speedup vs baseline: 2.2369x; 1.7965x over previous
#include <cuda_runtime.h>
#include <cuda_fp16.h>
#include <math.h>

#define LYRS 12
#define NH 12
#define DMODEL 768
#define DHEAD 64
#define DMLP 3072
#define NVOCAB 50257
#define NVPAD 50304
#define BATCH 2
#define SEQ 1024
#define MROWS 2048

// ---- scratch (device globals; no allocation allowed) ----
__device__ float  g_resid[MROWS*DMODEL];
__device__ __half g_x[MROWS*DMODEL];
__device__ __half g_q[MROWS*DMODEL];
__device__ __half g_k[MROWS*DMODEL];
__device__ __half g_v[MROWS*DMODEL];
__device__ __half g_z[MROWS*DMODEL];
__device__ __half g_h[MROWS*DMLP];
// repacked K-major [N][K] fp16, 32-wide k-interleaved weights
__device__ __half g_bq[LYRS*DMODEL*DMODEL];
__device__ __half g_bk[LYRS*DMODEL*DMODEL];
__device__ __half g_bv[LYRS*DMODEL*DMODEL];
__device__ __half g_bo[LYRS*DMODEL*DMODEL];
__device__ __half g_bin[LYRS*DMLP*DMODEL];
__device__ __half g_bout[LYRS*DMODEL*DMLP];
__device__ __half g_bu[(long)NVPAD*DMODEL];

// 32-wide k-interleave (fragment-pair contiguity for m16n8k16 LDS.128 loads)
__device__ __forceinline__ int kperm(int c) {
    return (c & ~31) | (((c >> 1) & 3) << 3) | (((c >> 4) & 1) << 2)
         | (((c >> 3) & 1) << 1) | (c & 1);
}
__device__ __forceinline__ void cpa16(__half* dst, const __half* src) {
    unsigned d = (unsigned)__cvta_generic_to_shared(dst);
    asm volatile("cp.async.cg.shared.global [%0], [%1], 16;" :: "r"(d), "l"(src));
}
#define MMA16816(D, A0,A1,A2,A3, B0,B1) \
    asm volatile("mma.sync.aligned.m16n8k16.row.col.f32.f16.f16.f32 " \
        "{%0,%1,%2,%3}, {%4,%5,%6,%7}, {%8,%9}, {%0,%1,%2,%3};" \
        : "+f"(D[0]), "+f"(D[1]), "+f"(D[2]), "+f"(D[3]) \
        : "r"(A0), "r"(A1), "r"(A2), "r"(A3), "r"(B0), "r"(B1))

// ---- embedding ----
__global__ void embed_kernel(const int* __restrict__ tokens, const float* __restrict__ WE,
                             const float* __restrict__ Wpos, float* __restrict__ resid)
{
    int idx = blockIdx.x * blockDim.x + threadIdx.x;
    if (idx >= MROWS*DMODEL) return;
    int d = idx % DMODEL, bs = idx / DMODEL, s = bs % SEQ;
    resid[idx] = WE[(long)tokens[bs]*DMODEL + d] + Wpos[s*DMODEL + d];
}

// ---- layernorm: fp32 input, fp16 k-interleaved output ----
__global__ void layernorm_kernel(const float* __restrict__ in, const float* __restrict__ w,
                                 const float* __restrict__ b, __half* __restrict__ out)
{
    __shared__ float sm[16];
    int row = blockIdx.x, tid = threadIdx.x;
    const float* x = in + (long)row * DMODEL;
    float s = 0.f, ss = 0.f;
    for (int i = tid; i < DMODEL; i += 256) { float v = x[i]; s += v; ss += v*v; }
    #pragma unroll
    for (int o = 16; o > 0; o >>= 1) {
        s  += __shfl_xor_sync(0xffffffffu, s,  o);
        ss += __shfl_xor_sync(0xffffffffu, ss, o);
    }
    if ((tid & 31) == 0) { sm[tid>>5] = s; sm[8 + (tid>>5)] = ss; }
    __syncthreads();
    if (tid < 8) {
        float a = sm[tid], c = sm[8+tid];
        #pragma unroll
        for (int o = 4; o > 0; o >>= 1) {
            a += __shfl_xor_sync(0xffu, a, o);
            c += __shfl_xor_sync(0xffu, c, o);
        }
        if (tid == 0) { sm[0] = a; sm[8] = c; }
    }
    __syncthreads();
    float mean = sm[0] * (1.f/DMODEL);
    float var  = sm[8] * (1.f/DMODEL) - mean*mean;
    float inv  = rsqrtf(var + 1e-5f);
    for (int i = tid; i < DMODEL; i += 256)
        out[(long)row*DMODEL + kperm(i)] = __float2half((x[i]-mean)*inv*w[i] + b[i]);
}

// ---- weight repack: per-head [L][H][D][DH] -> [L][h*64+e][perm(D)] (fp16) ----
__global__ void trans_head(const float* __restrict__ src, __half* __restrict__ dst)
{
    __shared__ float t[32][33];
    int tx = threadIdx.x, ty = threadIdx.y;
    int d0 = blockIdx.x*32, e0 = blockIdx.y*32, lh = blockIdx.z;
    int l = lh / NH, h = lh % NH;
    const float* sp = src + (long)lh*DMODEL*DHEAD;
    __half* dp = dst + (long)l*DMODEL*DMODEL;
    #pragma unroll
    for (int i = 0; i < 4; i++)
        t[ty+8*i][tx] = sp[(long)(d0+ty+8*i)*DHEAD + e0+tx];
    __syncthreads();
    #pragma unroll
    for (int i = 0; i < 4; i++)
        dp[(long)(h*64 + e0+ty+8*i)*DMODEL + kperm(d0+tx)] = __float2half(t[tx][ty+8*i]);
}

// ---- weight repack: [K,N] -> [Npad][perm(K)] transpose (fp16, zero pad) ----
__global__ void trans_kn(const float* __restrict__ src, __half* __restrict__ dst,
                         int K, int N, int Npad)
{
    __shared__ float t[32][33];
    int tx = threadIdx.x, ty = threadIdx.y;
    int n0 = blockIdx.x*32, k0 = blockIdx.y*32, l = blockIdx.z;
    const float* sp = src + (long)l*K*N;
    __half* dp = dst + (long)l*Npad*K;
    #pragma unroll
    for (int i = 0; i < 4; i++) {
        int n = n0+tx;
        t[ty+8*i][tx] = (n < N) ? sp[(long)(k0+ty+8*i)*N + n] : 0.f;
    }
    __syncthreads();
    #pragma unroll
    for (int i = 0; i < 4; i++)
        dp[(long)(n0+ty+8*i)*K + kperm(k0+tx)] = __float2half(t[tx][ty+8*i]);
}

// ---- fp16 mma.sync GEMM (r13 champion core) ----
// OUTM: 0 = fp32 natural, 1 = fp16 kperm, 2 = fp16 natural
#define KLDH 40
#define CLD 132

template<int TM, bool GELU, bool RES, int OUTM>
__device__ __forceinline__ void gemm_core(
    const __half* __restrict__ A, const __half* __restrict__ B,
    const float* __restrict__ bias, const float* __restrict__ res,
    void* __restrict__ Cv, int K, int nvalid)
{
    extern __shared__ char smraw[];
    __half* smh = (__half*)smraw;
    const int STAGEH = (TM + 128)*KLDH;
    const int MF = TM/32;
    int tid = threadIdx.x, wid = tid >> 5, lane = tid & 31;
    int gid = lane >> 2, tig = lane & 3;
    int bm = blockIdx.y * TM, bn = blockIdx.x * 128;
    int wm = (wid >> 2) * (TM/2);
    int wn = (wid & 3) * 32;

    float d[TM/32][4][4];
    #pragma unroll
    for (int mi = 0; mi < MF; mi++)
        #pragma unroll
        for (int ni = 0; ni < 4; ni++)
            #pragma unroll
            for (int r = 0; r < 4; r++) d[mi][ni][r] = 0.f;

    auto loadStage = [&](int s, int it) {
        __half* as = smh + s*STAGEH;
        __half* bs = as + TM*KLDH;
        const __half* Ag = A + (long)bm*K + it*32;
        const __half* Bg = B + (long)bn*K + it*32;
        #pragma unroll
        for (int i = 0; i < TM/64; i++) {
            int idx = tid + 256*i;
            int row = idx >> 2, c = idx & 3;
            cpa16(as + row*KLDH + c*8, Ag + (long)row*K + c*8);
        }
        #pragma unroll
        for (int i = 0; i < 2; i++) {
            int idx = tid + 256*i;
            int row = idx >> 2, c = idx & 3;
            cpa16(bs + row*KLDH + c*8, Bg + (long)row*K + c*8);
        }
        asm volatile("cp.async.commit_group;" ::);
    };

    const int nIter = K >> 5;
    loadStage(0, 0);
    loadStage(1, 1);

    for (int it = 0; it < nIter; it++) {
        int cur = it % 3;
        if (it + 2 < nIter) asm volatile("cp.async.wait_group 1;" ::);
        else                asm volatile("cp.async.wait_group 0;" ::);
        __syncthreads();
        if (it + 2 < nIter) loadStage((it+2) % 3, it+2);

        const __half* as = smh + cur*STAGEH;
        const __half* bs = as + TM*KLDH;
        uint4 av0[TM/32], av1[TM/32], bv[4];
        #pragma unroll
        for (int mi = 0; mi < MF; mi++) {
            av0[mi] = ((const uint4*)(as + (wm + mi*16 + gid)*KLDH))[tig];
            av1[mi] = ((const uint4*)(as + (wm + mi*16 + gid + 8)*KLDH))[tig];
        }
        #pragma unroll
        for (int ni = 0; ni < 4; ni++)
            bv[ni] = ((const uint4*)(bs + (wn + ni*8 + gid)*KLDH))[tig];

        #pragma unroll
        for (int mi = 0; mi < MF; mi++)
            #pragma unroll
            for (int ni = 0; ni < 4; ni++)
                MMA16816(d[mi][ni], av0[mi].x, av1[mi].x, av0[mi].y, av1[mi].y,
                         bv[ni].x, bv[ni].y);
        #pragma unroll
        for (int mi = 0; mi < MF; mi++)
            #pragma unroll
            for (int ni = 0; ni < 4; ni++)
                MMA16816(d[mi][ni], av0[mi].z, av1[mi].z, av0[mi].w, av1[mi].w,
                         bv[ni].z, bv[ni].w);
        __syncthreads();
    }

    float* Cs = (float*)smraw;
    #pragma unroll
    for (int mi = 0; mi < MF; mi++)
        #pragma unroll
        for (int ni = 0; ni < 4; ni++) {
            float* dd = d[mi][ni];
            int col = wn + ni*8 + 2*tig;
            float* p0 = Cs + (wm + mi*16 + gid)*CLD + col;
            float* p1 = Cs + (wm + mi*16 + gid + 8)*CLD + col;
            p0[0] = dd[0]; p0[1] = dd[1];
            p1[0] = dd[2]; p1[1] = dd[3];
        }
    __syncthreads();

    for (int idx = tid; idx < TM*128; idx += 256) {
        int r = idx >> 7, c = idx & 127;
        int n = bn + c;
        if (n < nvalid) {
            float v = Cs[r*CLD + c] + bias[n];
            long gr = bm + r;
            if (RES) v += res[gr*nvalid + n];
            if (GELU) {
                float t3 = v*v*v;
                v = 0.5f*v*(1.f + tanhf(0.7978845608028654f*(v + 0.044715f*t3)));
            }
            if (OUTM == 0)      ((float*)Cv)[gr*nvalid + n] = v;
            else if (OUTM == 1) ((__half*)Cv)[gr*nvalid + kperm(n)] = __float2half(v);
            else                ((__half*)Cv)[gr*nvalid + n] = __float2half(v);
        }
    }
}

template<int TM, bool GELU, bool RES, int OUTM>
__global__ void __launch_bounds__(256, 2) gemm_w(
    const __half* __restrict__ A, const __half* __restrict__ B,
    const float* __restrict__ bias, const float* __restrict__ res,
    void* __restrict__ C, int K, int nvalid)
{
    gemm_core<TM,GELU,RES,OUTM>(A, B, bias, res, C, K, nvalid);
}

__global__ void __launch_bounds__(256, 2) qkv_w(
    const __half* __restrict__ A,
    const __half* __restrict__ Bq, const __half* __restrict__ Bk, const __half* __restrict__ Bv,
    const float* __restrict__ bq, const float* __restrict__ bk, const float* __restrict__ bv,
    __half* __restrict__ q, __half* __restrict__ k, __half* __restrict__ v)
{
    const __half* B; const float* bias; __half* C;
    int z = blockIdx.z;
    if (z == 0)      { B = Bq; bias = bq; C = q; }
    else if (z == 1) { B = Bk; bias = bk; C = k; }
    else             { B = Bv; bias = bv; C = v; }
    gemm_core<128,false,false,2>(A, B, bias, nullptr, C, DMODEL, DMODEL);
}

// ---- tensor-core flash attention ----
// block = 128 threads (4 warps), grid (SEQ/64, NH, BATCH).
// Warp w owns q-rows [w*16, w*16+16). S=QK^T and PV via m16n8k16;
// online softmax in fragments (lane-quad shuffles), V staged transposed.
#define QLD 72
#define VLD 40

__global__ void __launch_bounds__(128) flash_kernel(
    const __half* __restrict__ q, const __half* __restrict__ k,
    const __half* __restrict__ v, __half* __restrict__ z)
{
    __shared__ __half Qs[64][QLD];
    __shared__ __half Ks[32][QLD];
    __shared__ __half Vt[64][VLD];
    int tid = threadIdx.x, wid = tid >> 5, lane = tid & 31;
    int gid = lane >> 2, tig = lane & 3;
    int qt = blockIdx.x, h = blockIdx.y, b = blockIdx.z;
    int wrow = wid * 16;
    long qbase = (long)(b*SEQ + qt*64)*DMODEL + h*64;

    // load Q tile 64x64 (vectorized, coalesced)
    #pragma unroll
    for (int i = 0; i < 4; i++) {
        int lin = tid + 128*i;            // 0..511, 8 halves each
        int row = lin >> 3, c8 = (lin & 7) * 8;
        *(uint4*)&Qs[row][c8] = *(const uint4*)&q[qbase + (long)row*DMODEL + c8];
    }

    float o[8][4];
    #pragma unroll
    for (int nf = 0; nf < 8; nf++)
        #pragma unroll
        for (int r = 0; r < 4; r++) o[nf][r] = 0.f;
    float m0 = -1e30f, m1 = -1e30f, l0 = 0.f, l1 = 0.f;

    int row0 = qt*64 + wrow + gid, row1 = row0 + 8;
    int ntiles = qt*2 + 2;

    for (int kt = 0; kt < ntiles; kt++) {
        __syncthreads();
        long kb = (long)(b*SEQ + kt*32)*DMODEL + h*64;
        #pragma unroll
        for (int i = 0; i < 2; i++) {
            int lin = tid + 128*i;        // 0..255
            int row = lin >> 3, c8 = (lin & 7) * 8;
            *(uint4*)&Ks[row][c8] = *(const uint4*)&k[kb + (long)row*DMODEL + c8];
        }
        #pragma unroll
        for (int i = 0; i < 16; i++) {
            int idx = tid + 128*i;        // 0..2047
            int key = idx >> 6, e = idx & 63;
            Vt[e][key] = v[kb + (long)key*DMODEL + e];
        }
        __syncthreads();

        // S = Q K^T : per warp 16x32, frags s[4][4]
        float s[4][4];
        #pragma unroll
        for (int nf = 0; nf < 4; nf++)
            #pragma unroll
            for (int r = 0; r < 4; r++) s[nf][r] = 0.f;
        #pragma unroll
        for (int ks = 0; ks < 4; ks++) {
            int kc = ks*16 + 2*tig;
            unsigned a0 = *(const unsigned*)&Qs[wrow+gid][kc];
            unsigned a1 = *(const unsigned*)&Qs[wrow+gid+8][kc];
            unsigned a2 = *(const unsigned*)&Qs[wrow+gid][kc+8];
            unsigned a3 = *(const unsigned*)&Qs[wrow+gid+8][kc+8];
            #pragma unroll
            for (int nf = 0; nf < 4; nf++) {
                unsigned b0 = *(const unsigned*)&Ks[nf*8+gid][kc];
                unsigned b1 = *(const unsigned*)&Ks[nf*8+gid][kc+8];
                MMA16816(s[nf], a0, a1, a2, a3, b0, b1);
            }
        }

        // scale + causal mask
        #pragma unroll
        for (int nf = 0; nf < 4; nf++) {
            int col = kt*32 + nf*8 + 2*tig;
            s[nf][0] = (col   <= row0) ? s[nf][0]*0.125f : -1e30f;
            s[nf][1] = (col+1 <= row0) ? s[nf][1]*0.125f : -1e30f;
            s[nf][2] = (col   <= row1) ? s[nf][2]*0.125f : -1e30f;
            s[nf][3] = (col+1 <= row1) ? s[nf][3]*0.125f : -1e30f;
        }
        // row maxima (2 rows/thread) + quad reduce
        float tm0 = -1e30f, tm1 = -1e30f;
        #pragma unroll
        for (int nf = 0; nf < 4; nf++) {
            tm0 = fmaxf(tm0, fmaxf(s[nf][0], s[nf][1]));
            tm1 = fmaxf(tm1, fmaxf(s[nf][2], s[nf][3]));
        }
        #pragma unroll
        for (int o2 = 1; o2 <= 2; o2 <<= 1) {
            tm0 = fmaxf(tm0, __shfl_xor_sync(0xffffffffu, tm0, o2));
            tm1 = fmaxf(tm1, __shfl_xor_sync(0xffffffffu, tm1, o2));
        }
        float mn0 = fmaxf(m0, tm0), mn1 = fmaxf(m1, tm1);
        float sc0 = __expf(m0 - mn0), sc1 = __expf(m1 - mn1);
        // p = exp(s - mn), row sums
        float ts0 = 0.f, ts1 = 0.f;
        #pragma unroll
        for (int nf = 0; nf < 4; nf++) {
            s[nf][0] = __expf(s[nf][0] - mn0);
            s[nf][1] = __expf(s[nf][1] - mn0);
            s[nf][2] = __expf(s[nf][2] - mn1);
            s[nf][3] = __expf(s[nf][3] - mn1);
            ts0 += s[nf][0] + s[nf][1];
            ts1 += s[nf][2] + s[nf][3];
        }
        #pragma unroll
        for (int o2 = 1; o2 <= 2; o2 <<= 1) {
            ts0 += __shfl_xor_sync(0xffffffffu, ts0, o2);
            ts1 += __shfl_xor_sync(0xffffffffu, ts1, o2);
        }
        l0 = l0*sc0 + ts0; l1 = l1*sc1 + ts1;
        m0 = mn0; m1 = mn1;
        #pragma unroll
        for (int nf = 0; nf < 8; nf++) {
            o[nf][0] *= sc0; o[nf][1] *= sc0;
            o[nf][2] *= sc1; o[nf][3] *= sc1;
        }
        // P fp16 A-operands: kk-step uses s-frags 2kk, 2kk+1
        unsigned pa[2][4];
        #pragma unroll
        for (int kk = 0; kk < 2; kk++) {
            __half2 h0 = __floats2half2_rn(s[2*kk][0],   s[2*kk][1]);
            __half2 h1 = __floats2half2_rn(s[2*kk][2],   s[2*kk][3]);
            __half2 h2 = __floats2half2_rn(s[2*kk+1][0], s[2*kk+1][1]);
            __half2 h3 = __floats2half2_rn(s[2*kk+1][2], s[2*kk+1][3]);
            pa[kk][0] = *(unsigned*)&h0;
            pa[kk][1] = *(unsigned*)&h1;
            pa[kk][2] = *(unsigned*)&h2;
            pa[kk][3] = *(unsigned*)&h3;
        }
        // O += P V : N=64 (8 frags), K=32 (2 k16 steps)
        #pragma unroll
        for (int kk = 0; kk < 2; kk++) {
            int kc = kk*16 + 2*tig;
            #pragma unroll
            for (int nf = 0; nf < 8; nf++) {
                unsigned b0 = *(const unsigned*)&Vt[nf*8+gid][kc];
                unsigned b1 = *(const unsigned*)&Vt[nf*8+gid][kc+8];
                MMA16816(o[nf], pa[kk][0], pa[kk][1], pa[kk][2], pa[kk][3], b0, b1);
            }
        }
    }

    float inv0 = 1.f / l0, inv1 = 1.f / l1;
    long zr0 = (long)(b*SEQ + qt*64 + wrow + gid)*DMODEL;
    long zr1 = zr0 + 8*DMODEL;
    #pragma unroll
    for (int nf = 0; nf < 8; nf++) {
        int e = nf*8 + 2*tig;
        int pe = kperm(h*64 + e);
        __half2 w0 = __floats2half2_rn(o[nf][0]*inv0, o[nf][1]*inv0);
        __half2 w1 = __floats2half2_rn(o[nf][2]*inv1, o[nf][3]*inv1);
        *(__half2*)&z[zr0 + pe] = w0;
        *(__half2*)&z[zr1 + pe] = w1;
    }
}

// smem bytes: max(3 fp16 stages, fp32 epilogue restage)
#define SMB128 (128*CLD*4)
#define SMB64  (3*(64+128)*KLDH*2 > 64*CLD*4 ? 3*(64+128)*KLDH*2 : 64*CLD*4)

extern "C" void kernel_launch(void* const* d_in, const int* in_sizes, int n_in,
                              void* d_out, int out_size)
{
    const int*   tokens = (const int*)  d_in[0];
    const float* W_E    = (const float*)d_in[1];
    const float* W_pos  = (const float*)d_in[2];
    const float* ln1_w  = (const float*)d_in[3];
    const float* ln1_b  = (const float*)d_in[4];
    const float* W_Q    = (const float*)d_in[5];
    const float* b_Q    = (const float*)d_in[6];
    const float* W_K    = (const float*)d_in[7];
    const float* b_K    = (const float*)d_in[8];
    const float* W_V    = (const float*)d_in[9];
    const float* b_V    = (const float*)d_in[10];
    const float* W_O    = (const float*)d_in[11];
    const float* b_O    = (const float*)d_in[12];
    const float* ln2_w  = (const float*)d_in[13];
    const float* ln2_b  = (const float*)d_in[14];
    const float* W_in   = (const float*)d_in[15];
    const float* b_in   = (const float*)d_in[16];
    const float* W_out  = (const float*)d_in[17];
    const float* b_out  = (const float*)d_in[18];
    const float* lnf_w  = (const float*)d_in[19];
    const float* lnf_b  = (const float*)d_in[20];
    const float* W_U    = (const float*)d_in[21];
    const float* b_U    = (const float*)d_in[22];
    float* out = (float*)d_out;

    float *p_resid;
    __half *p_x, *p_q, *p_k, *p_v, *p_z, *p_h;
    __half *p_bq, *p_bk, *p_bv, *p_bo, *p_bin, *p_bout, *p_bu;
    cudaGetSymbolAddress((void**)&p_resid, g_resid);
    cudaGetSymbolAddress((void**)&p_x, g_x);
    cudaGetSymbolAddress((void**)&p_q, g_q);
    cudaGetSymbolAddress((void**)&p_k, g_k);
    cudaGetSymbolAddress((void**)&p_v, g_v);
    cudaGetSymbolAddress((void**)&p_z, g_z);
    cudaGetSymbolAddress((void**)&p_h, g_h);
    cudaGetSymbolAddress((void**)&p_bq, g_bq);
    cudaGetSymbolAddress((void**)&p_bk, g_bk);
    cudaGetSymbolAddress((void**)&p_bv, g_bv);
    cudaGetSymbolAddress((void**)&p_bo, g_bo);
    cudaGetSymbolAddress((void**)&p_bin, g_bin);
    cudaGetSymbolAddress((void**)&p_bout, g_bout);
    cudaGetSymbolAddress((void**)&p_bu, g_bu);

    cudaFuncSetAttribute((const void*)gemm_w<128,false,false,0>, cudaFuncAttributeMaxDynamicSharedMemorySize, SMB128);
    cudaFuncSetAttribute((const void*)gemm_w<128,true,false,1>,  cudaFuncAttributeMaxDynamicSharedMemorySize, SMB128);
    cudaFuncSetAttribute((const void*)gemm_w<64,false,true,0>,   cudaFuncAttributeMaxDynamicSharedMemorySize, SMB64);
    cudaFuncSetAttribute((const void*)qkv_w,                     cudaFuncAttributeMaxDynamicSharedMemorySize, SMB128);

    dim3 tb(32, 8);
    trans_head<<<dim3(24, 2, LYRS*NH), tb>>>(W_Q, p_bq);
    trans_head<<<dim3(24, 2, LYRS*NH), tb>>>(W_K, p_bk);
    trans_head<<<dim3(24, 2, LYRS*NH), tb>>>(W_V, p_bv);
    trans_kn<<<dim3(24, 24, LYRS), tb>>>(W_O, p_bo, DMODEL, DMODEL, DMODEL);
    trans_kn<<<dim3(96, 24, LYRS), tb>>>(W_in, p_bin, DMODEL, DMLP, DMLP);
    trans_kn<<<dim3(24, 96, LYRS), tb>>>(W_out, p_bout, DMLP, DMODEL, DMODEL);
    trans_kn<<<dim3(NVPAD/32, 24, 1), tb>>>(W_U, p_bu, DMODEL, NVOCAB, NVPAD);

    embed_kernel<<<(MROWS*DMODEL + 255)/256, 256>>>(tokens, W_E, W_pos, p_resid);

    for (int l = 0; l < LYRS; l++) {
        layernorm_kernel<<<MROWS, 256>>>(p_resid, ln1_w + l*DMODEL, ln1_b + l*DMODEL, p_x);

        qkv_w<<<dim3(6, 16, 3), 256, SMB128>>>(
            p_x,
            p_bq + (long)l*DMODEL*DMODEL, p_bk + (long)l*DMODEL*DMODEL, p_bv + (long)l*DMODEL*DMODEL,
            b_Q + l*DMODEL, b_K + l*DMODEL, b_V + l*DMODEL,
            p_q, p_k, p_v);

        flash_kernel<<<dim3(SEQ/64, NH, BATCH), 128>>>(p_q, p_k, p_v, p_z);

        gemm_w<64,false,true,0><<<dim3(6, 32), 256, SMB64>>>(
            p_z, p_bo + (long)l*DMODEL*DMODEL, b_O + l*DMODEL, p_resid, p_resid,
            DMODEL, DMODEL);

        layernorm_kernel<<<MROWS, 256>>>(p_resid, ln2_w + l*DMODEL, ln2_b + l*DMODEL, p_x);

        gemm_w<128,true,false,1><<<dim3(24, 16), 256, SMB128>>>(
            p_x, p_bin + (long)l*DMLP*DMODEL, b_in + l*DMLP, nullptr, p_h,
            DMODEL, DMLP);

        gemm_w<64,false,true,0><<<dim3(6, 32), 256, SMB64>>>(
            p_h, p_bout + (long)l*DMODEL*DMLP, b_out + l*DMODEL, p_resid, p_resid,
            DMLP, DMODEL);
    }

    layernorm_kernel<<<MROWS, 256>>>(p_resid, lnf_w, lnf_b, p_x);

    gemm_w<128,false,false,0><<<dim3(NVPAD/128, 16), 256, SMB128>>>(
        p_x, p_bu, b_U, nullptr, out, DMODEL, NVOCAB);
}

// round 17
// speedup vs baseline: 2.2566x; 1.0088x over previous
#include <cuda_runtime.h>
#include <cuda_fp16.h>
#include <math.h>

#define LYRS 12
#define NH 12
#define DMODEL 768
#define DHEAD 64
#define DMLP 3072
#define NVOCAB 50257
#define NVPAD 50304
#define BATCH 2
#define SEQ 1024
#define MROWS 2048

// ---- scratch (device globals; no allocation allowed) ----
__device__ float  g_resid[MROWS*DMODEL];
__device__ __half g_x[MROWS*DMODEL];
__device__ __half g_q[MROWS*DMODEL];
__device__ __half g_k[MROWS*DMODEL];
__device__ __half g_v[MROWS*DMODEL];
__device__ __half g_z[MROWS*DMODEL];
__device__ __half g_h[MROWS*DMLP];
// repacked K-major [N][K] fp16, 32-wide k-interleaved weights
__device__ __half g_bq[LYRS*DMODEL*DMODEL];
__device__ __half g_bk[LYRS*DMODEL*DMODEL];
__device__ __half g_bv[LYRS*DMODEL*DMODEL];
__device__ __half g_bo[LYRS*DMODEL*DMODEL];
__device__ __half g_bin[LYRS*DMLP*DMODEL];
__device__ __half g_bout[LYRS*DMODEL*DMLP];
__device__ __half g_bu[(long)NVPAD*DMODEL];

// 32-wide k-interleave (fragment-pair contiguity for m16n8k16 LDS.128 loads)
__device__ __forceinline__ int kperm(int c) {
    return (c & ~31) | (((c >> 1) & 3) << 3) | (((c >> 4) & 1) << 2)
         | (((c >> 3) & 1) << 1) | (c & 1);
}
__device__ __forceinline__ void cpa16(__half* dst, const __half* src) {
    unsigned d = (unsigned)__cvta_generic_to_shared(dst);
    asm volatile("cp.async.cg.shared.global [%0], [%1], 16;" :: "r"(d), "l"(src));
}
#define MMA16816(D, A0,A1,A2,A3, B0,B1) \
    asm volatile("mma.sync.aligned.m16n8k16.row.col.f32.f16.f16.f32 " \
        "{%0,%1,%2,%3}, {%4,%5,%6,%7}, {%8,%9}, {%0,%1,%2,%3};" \
        : "+f"(D[0]), "+f"(D[1]), "+f"(D[2]), "+f"(D[3]) \
        : "r"(A0), "r"(A1), "r"(A2), "r"(A3), "r"(B0), "r"(B1))

// ---- embedding ----
__global__ void embed_kernel(const int* __restrict__ tokens, const float* __restrict__ WE,
                             const float* __restrict__ Wpos, float* __restrict__ resid)
{
    int idx = blockIdx.x * blockDim.x + threadIdx.x;
    if (idx >= MROWS*DMODEL) return;
    int d = idx % DMODEL, bs = idx / DMODEL, s = bs % SEQ;
    resid[idx] = WE[(long)tokens[bs]*DMODEL + d] + Wpos[s*DMODEL + d];
}

// ---- layernorm: fp32 input, fp16 k-interleaved output ----
__global__ void layernorm_kernel(const float* __restrict__ in, const float* __restrict__ w,
                                 const float* __restrict__ b, __half* __restrict__ out)
{
    __shared__ float sm[16];
    int row = blockIdx.x, tid = threadIdx.x;
    const float* x = in + (long)row * DMODEL;
    float s = 0.f, ss = 0.f;
    for (int i = tid; i < DMODEL; i += 256) { float v = x[i]; s += v; ss += v*v; }
    #pragma unroll
    for (int o = 16; o > 0; o >>= 1) {
        s  += __shfl_xor_sync(0xffffffffu, s,  o);
        ss += __shfl_xor_sync(0xffffffffu, ss, o);
    }
    if ((tid & 31) == 0) { sm[tid>>5] = s; sm[8 + (tid>>5)] = ss; }
    __syncthreads();
    if (tid < 8) {
        float a = sm[tid], c = sm[8+tid];
        #pragma unroll
        for (int o = 4; o > 0; o >>= 1) {
            a += __shfl_xor_sync(0xffu, a, o);
            c += __shfl_xor_sync(0xffu, c, o);
        }
        if (tid == 0) { sm[0] = a; sm[8] = c; }
    }
    __syncthreads();
    float mean = sm[0] * (1.f/DMODEL);
    float var  = sm[8] * (1.f/DMODEL) - mean*mean;
    float inv  = rsqrtf(var + 1e-5f);
    for (int i = tid; i < DMODEL; i += 256)
        out[(long)row*DMODEL + kperm(i)] = __float2half((x[i]-mean)*inv*w[i] + b[i]);
}

// ---- weight repack: per-head [L][H][D][DH] -> [L][h*64+e][perm(D)] (fp16) ----
__global__ void trans_head(const float* __restrict__ src, __half* __restrict__ dst)
{
    __shared__ float t[32][33];
    int tx = threadIdx.x, ty = threadIdx.y;
    int d0 = blockIdx.x*32, e0 = blockIdx.y*32, lh = blockIdx.z;
    int l = lh / NH, h = lh % NH;
    const float* sp = src + (long)lh*DMODEL*DHEAD;
    __half* dp = dst + (long)l*DMODEL*DMODEL;
    #pragma unroll
    for (int i = 0; i < 4; i++)
        t[ty+8*i][tx] = sp[(long)(d0+ty+8*i)*DHEAD + e0+tx];
    __syncthreads();
    #pragma unroll
    for (int i = 0; i < 4; i++)
        dp[(long)(h*64 + e0+ty+8*i)*DMODEL + kperm(d0+tx)] = __float2half(t[tx][ty+8*i]);
}

// ---- weight repack: [K,N] -> [Npad][perm(K)] transpose (fp16, zero pad) ----
__global__ void trans_kn(const float* __restrict__ src, __half* __restrict__ dst,
                         int K, int N, int Npad)
{
    __shared__ float t[32][33];
    int tx = threadIdx.x, ty = threadIdx.y;
    int n0 = blockIdx.x*32, k0 = blockIdx.y*32, l = blockIdx.z;
    const float* sp = src + (long)l*K*N;
    __half* dp = dst + (long)l*Npad*K;
    #pragma unroll
    for (int i = 0; i < 4; i++) {
        int n = n0+tx;
        t[ty+8*i][tx] = (n < N) ? sp[(long)(k0+ty+8*i)*N + n] : 0.f;
    }
    __syncthreads();
    #pragma unroll
    for (int i = 0; i < 4; i++)
        dp[(long)(n0+ty+8*i)*K + kperm(k0+tx)] = __float2half(t[tx][ty+8*i]);
}

// ---- fp16 mma.sync GEMM: 4-stage cp.async, one sync per iter ----
// OUTM: 0 = fp32 natural, 1 = fp16 kperm, 2 = fp16 natural
#define KLDH 40
#define CLD 132

template<int TM, bool GELU, bool RES, int OUTM>
__device__ __forceinline__ void gemm_core(
    const __half* __restrict__ A, const __half* __restrict__ B,
    const float* __restrict__ bias, const float* __restrict__ res,
    void* __restrict__ Cv, int K, int nvalid)
{
    extern __shared__ char smraw[];
    __half* smh = (__half*)smraw;
    const int STAGEH = (TM + 128)*KLDH;
    const int MF = TM/32;
    int tid = threadIdx.x, wid = tid >> 5, lane = tid & 31;
    int gid = lane >> 2, tig = lane & 3;
    int bm = blockIdx.y * TM, bn = blockIdx.x * 128;
    int wm = (wid >> 2) * (TM/2);
    int wn = (wid & 3) * 32;

    float d[TM/32][4][4];
    #pragma unroll
    for (int mi = 0; mi < MF; mi++)
        #pragma unroll
        for (int ni = 0; ni < 4; ni++)
            #pragma unroll
            for (int r = 0; r < 4; r++) d[mi][ni][r] = 0.f;

    auto loadStage = [&](int s, int it) {
        __half* as = smh + s*STAGEH;
        __half* bs = as + TM*KLDH;
        const __half* Ag = A + (long)bm*K + it*32;
        const __half* Bg = B + (long)bn*K + it*32;
        #pragma unroll
        for (int i = 0; i < TM/64; i++) {
            int idx = tid + 256*i;
            int row = idx >> 2, c = idx & 3;
            cpa16(as + row*KLDH + c*8, Ag + (long)row*K + c*8);
        }
        #pragma unroll
        for (int i = 0; i < 2; i++) {
            int idx = tid + 256*i;
            int row = idx >> 2, c = idx & 3;
            cpa16(bs + row*KLDH + c*8, Bg + (long)row*K + c*8);
        }
        asm volatile("cp.async.commit_group;" ::);
    };

    const int nIter = K >> 5;    // >= 24 for all our GEMMs
    loadStage(0, 0);
    loadStage(1, 1);
    loadStage(2, 2);

    for (int it = 0; it < nIter; it++) {
        int cur = it & 3;
        if (it + 3 < nIter) asm volatile("cp.async.wait_group 2;" ::);
        else                asm volatile("cp.async.wait_group 0;" ::);
        __syncthreads();
        if (it + 3 < nIter) loadStage((it+3) & 3, it+3);

        const __half* as = smh + cur*STAGEH;
        const __half* bs = as + TM*KLDH;
        uint4 av0[TM/32], av1[TM/32], bv[4];
        #pragma unroll
        for (int mi = 0; mi < MF; mi++) {
            av0[mi] = ((const uint4*)(as + (wm + mi*16 + gid)*KLDH))[tig];
            av1[mi] = ((const uint4*)(as + (wm + mi*16 + gid + 8)*KLDH))[tig];
        }
        #pragma unroll
        for (int ni = 0; ni < 4; ni++)
            bv[ni] = ((const uint4*)(bs + (wn + ni*8 + gid)*KLDH))[tig];

        #pragma unroll
        for (int mi = 0; mi < MF; mi++)
            #pragma unroll
            for (int ni = 0; ni < 4; ni++)
                MMA16816(d[mi][ni], av0[mi].x, av1[mi].x, av0[mi].y, av1[mi].y,
                         bv[ni].x, bv[ni].y);
        #pragma unroll
        for (int mi = 0; mi < MF; mi++)
            #pragma unroll
            for (int ni = 0; ni < 4; ni++)
                MMA16816(d[mi][ni], av0[mi].z, av1[mi].z, av0[mi].w, av1[mi].w,
                         bv[ni].z, bv[ni].w);
        // no trailing sync: next iteration's top sync orders compute vs the
        // loadStage that overwrites this stage.
    }
    // guard the stage<->epilogue smem alias
    __syncthreads();

    float* Cs = (float*)smraw;
    #pragma unroll
    for (int mi = 0; mi < MF; mi++)
        #pragma unroll
        for (int ni = 0; ni < 4; ni++) {
            float* dd = d[mi][ni];
            int col = wn + ni*8 + 2*tig;
            float* p0 = Cs + (wm + mi*16 + gid)*CLD + col;
            float* p1 = Cs + (wm + mi*16 + gid + 8)*CLD + col;
            p0[0] = dd[0]; p0[1] = dd[1];
            p1[0] = dd[2]; p1[1] = dd[3];
        }
    __syncthreads();

    for (int idx = tid; idx < TM*128; idx += 256) {
        int r = idx >> 7, c = idx & 127;
        int n = bn + c;
        if (n < nvalid) {
            float v = Cs[r*CLD + c] + bias[n];
            long gr = bm + r;
            if (RES) v += res[gr*nvalid + n];
            if (GELU) {
                float t3 = v*v*v;
                v = 0.5f*v*(1.f + tanhf(0.7978845608028654f*(v + 0.044715f*t3)));
            }
            if (OUTM == 0)      ((float*)Cv)[gr*nvalid + n] = v;
            else if (OUTM == 1) ((__half*)Cv)[gr*nvalid + kperm(n)] = __float2half(v);
            else                ((__half*)Cv)[gr*nvalid + n] = __float2half(v);
        }
    }
}

template<int TM, bool GELU, bool RES, int OUTM>
__global__ void __launch_bounds__(256, 2) gemm_w(
    const __half* __restrict__ A, const __half* __restrict__ B,
    const float* __restrict__ bias, const float* __restrict__ res,
    void* __restrict__ C, int K, int nvalid)
{
    gemm_core<TM,GELU,RES,OUTM>(A, B, bias, res, C, K, nvalid);
}

__global__ void __launch_bounds__(256, 2) qkv_w(
    const __half* __restrict__ A,
    const __half* __restrict__ Bq, const __half* __restrict__ Bk, const __half* __restrict__ Bv,
    const float* __restrict__ bq, const float* __restrict__ bk, const float* __restrict__ bv,
    __half* __restrict__ q, __half* __restrict__ k, __half* __restrict__ v)
{
    const __half* B; const float* bias; __half* C;
    int z = blockIdx.z;
    if (z == 0)      { B = Bq; bias = bq; C = q; }
    else if (z == 1) { B = Bk; bias = bk; C = k; }
    else             { B = Bv; bias = bv; C = v; }
    gemm_core<128,false,false,2>(A, B, bias, nullptr, C, DMODEL, DMODEL);
}

// ---- tensor-core flash attention (r16 champion, unchanged) ----
#define QLD 72
#define VLD 40

__global__ void __launch_bounds__(128) flash_kernel(
    const __half* __restrict__ q, const __half* __restrict__ k,
    const __half* __restrict__ v, __half* __restrict__ z)
{
    __shared__ __half Qs[64][QLD];
    __shared__ __half Ks[32][QLD];
    __shared__ __half Vt[64][VLD];
    int tid = threadIdx.x, wid = tid >> 5, lane = tid & 31;
    int gid = lane >> 2, tig = lane & 3;
    int qt = blockIdx.x, h = blockIdx.y, b = blockIdx.z;
    int wrow = wid * 16;
    long qbase = (long)(b*SEQ + qt*64)*DMODEL + h*64;

    #pragma unroll
    for (int i = 0; i < 4; i++) {
        int lin = tid + 128*i;
        int row = lin >> 3, c8 = (lin & 7) * 8;
        *(uint4*)&Qs[row][c8] = *(const uint4*)&q[qbase + (long)row*DMODEL + c8];
    }

    float o[8][4];
    #pragma unroll
    for (int nf = 0; nf < 8; nf++)
        #pragma unroll
        for (int r = 0; r < 4; r++) o[nf][r] = 0.f;
    float m0 = -1e30f, m1 = -1e30f, l0 = 0.f, l1 = 0.f;

    int row0 = qt*64 + wrow + gid, row1 = row0 + 8;
    int ntiles = qt*2 + 2;

    for (int kt = 0; kt < ntiles; kt++) {
        __syncthreads();
        long kb = (long)(b*SEQ + kt*32)*DMODEL + h*64;
        #pragma unroll
        for (int i = 0; i < 2; i++) {
            int lin = tid + 128*i;
            int row = lin >> 3, c8 = (lin & 7) * 8;
            *(uint4*)&Ks[row][c8] = *(const uint4*)&k[kb + (long)row*DMODEL + c8];
        }
        #pragma unroll
        for (int i = 0; i < 16; i++) {
            int idx = tid + 128*i;
            int key = idx >> 6, e = idx & 63;
            Vt[e][key] = v[kb + (long)key*DMODEL + e];
        }
        __syncthreads();

        float s[4][4];
        #pragma unroll
        for (int nf = 0; nf < 4; nf++)
            #pragma unroll
            for (int r = 0; r < 4; r++) s[nf][r] = 0.f;
        #pragma unroll
        for (int ks = 0; ks < 4; ks++) {
            int kc = ks*16 + 2*tig;
            unsigned a0 = *(const unsigned*)&Qs[wrow+gid][kc];
            unsigned a1 = *(const unsigned*)&Qs[wrow+gid+8][kc];
            unsigned a2 = *(const unsigned*)&Qs[wrow+gid][kc+8];
            unsigned a3 = *(const unsigned*)&Qs[wrow+gid+8][kc+8];
            #pragma unroll
            for (int nf = 0; nf < 4; nf++) {
                unsigned b0 = *(const unsigned*)&Ks[nf*8+gid][kc];
                unsigned b1 = *(const unsigned*)&Ks[nf*8+gid][kc+8];
                MMA16816(s[nf], a0, a1, a2, a3, b0, b1);
            }
        }

        #pragma unroll
        for (int nf = 0; nf < 4; nf++) {
            int col = kt*32 + nf*8 + 2*tig;
            s[nf][0] = (col   <= row0) ? s[nf][0]*0.125f : -1e30f;
            s[nf][1] = (col+1 <= row0) ? s[nf][1]*0.125f : -1e30f;
            s[nf][2] = (col   <= row1) ? s[nf][2]*0.125f : -1e30f;
            s[nf][3] = (col+1 <= row1) ? s[nf][3]*0.125f : -1e30f;
        }
        float tm0 = -1e30f, tm1 = -1e30f;
        #pragma unroll
        for (int nf = 0; nf < 4; nf++) {
            tm0 = fmaxf(tm0, fmaxf(s[nf][0], s[nf][1]));
            tm1 = fmaxf(tm1, fmaxf(s[nf][2], s[nf][3]));
        }
        #pragma unroll
        for (int o2 = 1; o2 <= 2; o2 <<= 1) {
            tm0 = fmaxf(tm0, __shfl_xor_sync(0xffffffffu, tm0, o2));
            tm1 = fmaxf(tm1, __shfl_xor_sync(0xffffffffu, tm1, o2));
        }
        float mn0 = fmaxf(m0, tm0), mn1 = fmaxf(m1, tm1);
        float sc0 = __expf(m0 - mn0), sc1 = __expf(m1 - mn1);
        float ts0 = 0.f, ts1 = 0.f;
        #pragma unroll
        for (int nf = 0; nf < 4; nf++) {
            s[nf][0] = __expf(s[nf][0] - mn0);
            s[nf][1] = __expf(s[nf][1] - mn0);
            s[nf][2] = __expf(s[nf][2] - mn1);
            s[nf][3] = __expf(s[nf][3] - mn1);
            ts0 += s[nf][0] + s[nf][1];
            ts1 += s[nf][2] + s[nf][3];
        }
        #pragma unroll
        for (int o2 = 1; o2 <= 2; o2 <<= 1) {
            ts0 += __shfl_xor_sync(0xffffffffu, ts0, o2);
            ts1 += __shfl_xor_sync(0xffffffffu, ts1, o2);
        }
        l0 = l0*sc0 + ts0; l1 = l1*sc1 + ts1;
        m0 = mn0; m1 = mn1;
        #pragma unroll
        for (int nf = 0; nf < 8; nf++) {
            o[nf][0] *= sc0; o[nf][1] *= sc0;
            o[nf][2] *= sc1; o[nf][3] *= sc1;
        }
        unsigned pa[2][4];
        #pragma unroll
        for (int kk = 0; kk < 2; kk++) {
            __half2 h0 = __floats2half2_rn(s[2*kk][0],   s[2*kk][1]);
            __half2 h1 = __floats2half2_rn(s[2*kk][2],   s[2*kk][3]);
            __half2 h2 = __floats2half2_rn(s[2*kk+1][0], s[2*kk+1][1]);
            __half2 h3 = __floats2half2_rn(s[2*kk+1][2], s[2*kk+1][3]);
            pa[kk][0] = *(unsigned*)&h0;
            pa[kk][1] = *(unsigned*)&h1;
            pa[kk][2] = *(unsigned*)&h2;
            pa[kk][3] = *(unsigned*)&h3;
        }
        #pragma unroll
        for (int kk = 0; kk < 2; kk++) {
            int kc = kk*16 + 2*tig;
            #pragma unroll
            for (int nf = 0; nf < 8; nf++) {
                unsigned b0 = *(const unsigned*)&Vt[nf*8+gid][kc];
                unsigned b1 = *(const unsigned*)&Vt[nf*8+gid][kc+8];
                MMA16816(o[nf], pa[kk][0], pa[kk][1], pa[kk][2], pa[kk][3], b0, b1);
            }
        }
    }

    float inv0 = 1.f / l0, inv1 = 1.f / l1;
    long zr0 = (long)(b*SEQ + qt*64 + wrow + gid)*DMODEL;
    long zr1 = zr0 + 8*DMODEL;
    #pragma unroll
    for (int nf = 0; nf < 8; nf++) {
        int e = nf*8 + 2*tig;
        int pe = kperm(h*64 + e);
        __half2 w0 = __floats2half2_rn(o[nf][0]*inv0, o[nf][1]*inv0);
        __half2 w1 = __floats2half2_rn(o[nf][2]*inv1, o[nf][3]*inv1);
        *(__half2*)&z[zr0 + pe] = w0;
        *(__half2*)&z[zr1 + pe] = w1;
    }
}

// smem bytes: max(4 fp16 stages, fp32 epilogue restage)
#define SMB128 (4*(128+128)*KLDH*2 > 128*CLD*4 ? 4*(128+128)*KLDH*2 : 128*CLD*4)  // 81920
#define SMB64  (4*(64+128)*KLDH*2 > 64*CLD*4 ? 4*(64+128)*KLDH*2 : 64*CLD*4)      // 61440

extern "C" void kernel_launch(void* const* d_in, const int* in_sizes, int n_in,
                              void* d_out, int out_size)
{
    const int*   tokens = (const int*)  d_in[0];
    const float* W_E    = (const float*)d_in[1];
    const float* W_pos  = (const float*)d_in[2];
    const float* ln1_w  = (const float*)d_in[3];
    const float* ln1_b  = (const float*)d_in[4];
    const float* W_Q    = (const float*)d_in[5];
    const float* b_Q    = (const float*)d_in[6];
    const float* W_K    = (const float*)d_in[7];
    const float* b_K    = (const float*)d_in[8];
    const float* W_V    = (const float*)d_in[9];
    const float* b_V    = (const float*)d_in[10];
    const float* W_O    = (const float*)d_in[11];
    const float* b_O    = (const float*)d_in[12];
    const float* ln2_w  = (const float*)d_in[13];
    const float* ln2_b  = (const float*)d_in[14];
    const float* W_in   = (const float*)d_in[15];
    const float* b_in   = (const float*)d_in[16];
    const float* W_out  = (const float*)d_in[17];
    const float* b_out  = (const float*)d_in[18];
    const float* lnf_w  = (const float*)d_in[19];
    const float* lnf_b  = (const float*)d_in[20];
    const float* W_U    = (const float*)d_in[21];
    const float* b_U    = (const float*)d_in[22];
    float* out = (float*)d_out;

    float *p_resid;
    __half *p_x, *p_q, *p_k, *p_v, *p_z, *p_h;
    __half *p_bq, *p_bk, *p_bv, *p_bo, *p_bin, *p_bout, *p_bu;
    cudaGetSymbolAddress((void**)&p_resid, g_resid);
    cudaGetSymbolAddress((void**)&p_x, g_x);
    cudaGetSymbolAddress((void**)&p_q, g_q);
    cudaGetSymbolAddress((void**)&p_k, g_k);
    cudaGetSymbolAddress((void**)&p_v, g_v);
    cudaGetSymbolAddress((void**)&p_z, g_z);
    cudaGetSymbolAddress((void**)&p_h, g_h);
    cudaGetSymbolAddress((void**)&p_bq, g_bq);
    cudaGetSymbolAddress((void**)&p_bk, g_bk);
    cudaGetSymbolAddress((void**)&p_bv, g_bv);
    cudaGetSymbolAddress((void**)&p_bo, g_bo);
    cudaGetSymbolAddress((void**)&p_bin, g_bin);
    cudaGetSymbolAddress((void**)&p_bout, g_bout);
    cudaGetSymbolAddress((void**)&p_bu, g_bu);

    cudaFuncSetAttribute((const void*)gemm_w<128,false,false,0>, cudaFuncAttributeMaxDynamicSharedMemorySize, SMB128);
    cudaFuncSetAttribute((const void*)gemm_w<128,true,false,1>,  cudaFuncAttributeMaxDynamicSharedMemorySize, SMB128);
    cudaFuncSetAttribute((const void*)gemm_w<64,false,true,0>,   cudaFuncAttributeMaxDynamicSharedMemorySize, SMB64);
    cudaFuncSetAttribute((const void*)qkv_w,                     cudaFuncAttributeMaxDynamicSharedMemorySize, SMB128);

    dim3 tb(32, 8);
    trans_head<<<dim3(24, 2, LYRS*NH), tb>>>(W_Q, p_bq);
    trans_head<<<dim3(24, 2, LYRS*NH), tb>>>(W_K, p_bk);
    trans_head<<<dim3(24, 2, LYRS*NH), tb>>>(W_V, p_bv);
    trans_kn<<<dim3(24, 24, LYRS), tb>>>(W_O, p_bo, DMODEL, DMODEL, DMODEL);
    trans_kn<<<dim3(96, 24, LYRS), tb>>>(W_in, p_bin, DMODEL, DMLP, DMLP);
    trans_kn<<<dim3(24, 96, LYRS), tb>>>(W_out, p_bout, DMLP, DMODEL, DMODEL);
    trans_kn<<<dim3(NVPAD/32, 24, 1), tb>>>(W_U, p_bu, DMODEL, NVOCAB, NVPAD);

    embed_kernel<<<(MROWS*DMODEL + 255)/256, 256>>>(tokens, W_E, W_pos, p_resid);

    for (int l = 0; l < LYRS; l++) {
        layernorm_kernel<<<MROWS, 256>>>(p_resid, ln1_w + l*DMODEL, ln1_b + l*DMODEL, p_x);

        qkv_w<<<dim3(6, 16, 3), 256, SMB128>>>(
            p_x,
            p_bq + (long)l*DMODEL*DMODEL, p_bk + (long)l*DMODEL*DMODEL, p_bv + (long)l*DMODEL*DMODEL,
            b_Q + l*DMODEL, b_K + l*DMODEL, b_V + l*DMODEL,
            p_q, p_k, p_v);

        flash_kernel<<<dim3(SEQ/64, NH, BATCH), 128>>>(p_q, p_k, p_v, p_z);

        gemm_w<64,false,true,0><<<dim3(6, 32), 256, SMB64>>>(
            p_z, p_bo + (long)l*DMODEL*DMODEL, b_O + l*DMODEL, p_resid, p_resid,
            DMODEL, DMODEL);

        layernorm_kernel<<<MROWS, 256>>>(p_resid, ln2_w + l*DMODEL, ln2_b + l*DMODEL, p_x);

        gemm_w<128,true,false,1><<<dim3(24, 16), 256, SMB128>>>(
            p_x, p_bin + (long)l*DMLP*DMODEL, b_in + l*DMLP, nullptr, p_h,
            DMODEL, DMLP);

        gemm_w<64,false,true,0><<<dim3(6, 32), 256, SMB64>>>(
            p_h, p_bout + (long)l*DMODEL*DMLP, b_out + l*DMODEL, p_resid, p_resid,
            DMLP, DMODEL);
    }

    layernorm_kernel<<<MROWS, 256>>>(p_resid, lnf_w, lnf_b, p_x);

    gemm_w<128,false,false,0><<<dim3(NVPAD/128, 16), 256, SMB128>>>(
        p_x, p_bu, b_U, nullptr, out, DMODEL, NVOCAB);
}